// round 2
// baseline (speedup 1.0000x reference)
#include <cuda_runtime.h>
#include <cuda_bf16.h>

#define NN 50000
#define EE 800000
#define BB 256
#define DD 128
#define LL 4

// ---------------- scratch (static device globals; no runtime alloc) ----------
__device__ __align__(16) float g_H [(size_t)NN * DD];
__device__ __align__(16) float g_X1[(size_t)NN * DD];
__device__ __align__(16) float g_X2[(size_t)NN * DD];
__device__ __align__(16) float g_T [(size_t)NN * DD];
__device__ __align__(16) float g_dsq[NN];
__device__ __align__(16) float g_w  [EE];
__device__            int    g_deg [NN];
__device__ __align__(16) float g_stats[2 * DD];
__device__ __align__(16) float g_pool [BB * DD];
__device__            int    g_cnt  [BB];

__device__ __forceinline__ void red_add_v4(float* p, float4 v) {
    asm volatile("red.global.add.v4.f32 [%0], {%1,%2,%3,%4};"
                 :: "l"(p), "f"(v.x), "f"(v.y), "f"(v.z), "f"(v.w) : "memory");
}

// ---------------- setup kernels ----------------------------------------------
__global__ void k_init() {
    int i = blockIdx.x * blockDim.x + threadIdx.x;
    if (i < NN) g_deg[i] = 0;
    if (i < BB * DD) g_pool[i] = 0.f;
    if (i < BB) g_cnt[i] = 0;
}

// one warp per node; lane handles 4 channels (float4)
__global__ void k_embed(const int* __restrict__ h_idx,
                        const float* __restrict__ atom_emb) {
    int w = (blockIdx.x * blockDim.x + threadIdx.x) >> 5;
    if (w >= NN) return;
    int lane = threadIdx.x & 31;
    float4 acc = make_float4(0.f, 0.f, 0.f, 0.f);
#pragma unroll
    for (int f = 0; f < 9; f++) {
        int id = __ldg(&h_idx[w * 9 + f]);
        const float4* p = (const float4*)(atom_emb + ((size_t)f * 100 + id) * DD);
        float4 v = p[lane];
        acc.x += v.x; acc.y += v.y; acc.z += v.z; acc.w += v.w;
    }
    *(float4*)(g_H + (size_t)w * DD + lane * 4) = acc;
}

__global__ void k_count(const int* __restrict__ dst) {
    int e = blockIdx.x * blockDim.x + threadIdx.x;
    if (e < EE) atomicAdd(&g_deg[dst[e]], 1);
}

__global__ void k_dsqrt() {
    int i = blockIdx.x * blockDim.x + threadIdx.x;
    if (i < NN) {
        float d = (float)max(g_deg[i], 1);
        g_dsq[i] = rsqrtf(d);
    }
}

__global__ void k_edgew(const int* __restrict__ src, const int* __restrict__ dst) {
    int e = blockIdx.x * blockDim.x + threadIdx.x;
    if (e < EE) g_w[e] = g_dsq[src[e]] * g_dsq[dst[e]];
}

// ---------------- per-layer kernels ------------------------------------------
// X1 = 0 ; X2 = -H ; stats = 0
__global__ void k_prep() {
    int i = blockIdx.x * blockDim.x + threadIdx.x;  // float4 index
    if (i < NN * (DD / 4)) {
        ((float4*)g_X1)[i] = make_float4(0.f, 0.f, 0.f, 0.f);
        float4 h = ((const float4*)g_H)[i];
        ((float4*)g_X2)[i] = make_float4(-h.x, -h.y, -h.z, -h.w);
    }
    if (blockIdx.x == 0 && threadIdx.x < 2 * DD) g_stats[threadIdx.x] = 0.f;
}

// mode 0: X1 += coef * w_e * H[src]   (coef = -1)
// mode 1: X2 += coef * w_e * X1[src]  (coef = -2)
__global__ void k_edge(int mode, const int* __restrict__ src,
                       const int* __restrict__ dst, float coef) {
    int e = (blockIdx.x * blockDim.x + threadIdx.x) >> 5;
    if (e >= EE) return;
    int lane = threadIdx.x & 31;
    const float* x = (mode == 0) ? g_H : g_X1;
    float* out     = (mode == 0) ? g_X1 : g_X2;
    int s = __ldg(&src[e]);
    int d = __ldg(&dst[e]);
    float ww = __ldg(&g_w[e]) * coef;
    float4 v = *(const float4*)(x + (size_t)s * DD + lane * 4);
    red_add_v4(out + (size_t)d * DD + lane * 4,
               make_float4(v.x * ww, v.y * ww, v.z * ww, v.w * ww));
}

// T[n,:] = [H | X1 | X2][n,:] @ W   (W is [384,128] row-major)
#define BM 64
#define BN 128
#define BK 16
__global__ void __launch_bounds__(256) k_gemm(const float* __restrict__ W) {
    __shared__ __align__(16) float As[BK][BM];   // transposed A chunk
    __shared__ __align__(16) float Ws[BK][BN];
    int tid = threadIdx.x;
    int tx = tid & 31;   // col group -> cols tx*4..tx*4+3
    int ty = tid >> 5;   // row group -> rows ty*8..ty*8+7
    int row0 = blockIdx.x * BM;
    float acc[8][4] = {};
    for (int k0 = 0; k0 < 3 * DD; k0 += BK) {
        // A tile: 64 rows x 16 k, 4 floats per thread
        {
            int r = tid >> 2;
            int kk = (tid & 3) * 4;
            int grow = row0 + r;
            int gk = k0 + kk;
            const float* srcm = (gk < DD) ? g_H : ((gk < 2 * DD) ? g_X1 : g_X2);
            int kin = gk & (DD - 1);
            float4 v = make_float4(0.f, 0.f, 0.f, 0.f);
            if (grow < NN) v = *(const float4*)(srcm + (size_t)grow * DD + kin);
            As[kk + 0][r] = v.x; As[kk + 1][r] = v.y;
            As[kk + 2][r] = v.z; As[kk + 3][r] = v.w;
        }
        // W tile: 16 x 128, 8 floats per thread (2 float4)
        {
            int i = tid * 4;
            int kk = i >> 7, c = i & 127;
            *(float4*)&Ws[kk][c] = *(const float4*)(W + (size_t)(k0 + kk) * DD + c);
            i += 1024;
            kk = i >> 7; c = i & 127;
            *(float4*)&Ws[kk][c] = *(const float4*)(W + (size_t)(k0 + kk) * DD + c);
        }
        __syncthreads();
#pragma unroll
        for (int kk = 0; kk < BK; kk++) {
            float4 a0 = *(const float4*)&As[kk][ty * 8];
            float4 a1 = *(const float4*)&As[kk][ty * 8 + 4];
            float4 w4 = *(const float4*)&Ws[kk][tx * 4];
            float ar[8] = {a0.x, a0.y, a0.z, a0.w, a1.x, a1.y, a1.z, a1.w};
            float wr[4] = {w4.x, w4.y, w4.z, w4.w};
#pragma unroll
            for (int i = 0; i < 8; i++)
#pragma unroll
                for (int j = 0; j < 4; j++)
                    acc[i][j] += ar[i] * wr[j];
        }
        __syncthreads();
    }
#pragma unroll
    for (int i = 0; i < 8; i++) {
        int r = row0 + ty * 8 + i;
        if (r < NN)
            *(float4*)(g_T + (size_t)r * DD + tx * 4) =
                make_float4(acc[i][0], acc[i][1], acc[i][2], acc[i][3]);
    }
}

// per-channel sum & sumsq over T
__global__ void k_stats() {
    __shared__ float sh1[256], sh2[256];
    int col = threadIdx.x & 127;
    int half = threadIdx.x >> 7;
    int r0 = blockIdx.x * 256;
    int rend = min(r0 + 256, NN);
    float s = 0.f, s2 = 0.f;
    for (int r = r0 + half; r < rend; r += 2) {
        float v = g_T[(size_t)r * DD + col];
        s += v; s2 += v * v;
    }
    sh1[threadIdx.x] = s;
    sh2[threadIdx.x] = s2;
    __syncthreads();
    if (half == 0) {
        atomicAdd(&g_stats[col],      s  + sh1[threadIdx.x + 128]);
        atomicAdd(&g_stats[DD + col], s2 + sh2[threadIdx.x + 128]);
    }
}

// H += relu( (T - mu) * rstd * gamma + beta )
__global__ void k_bnres(const float* __restrict__ gamma,
                        const float* __restrict__ beta) {
    int i = blockIdx.x * blockDim.x + threadIdx.x;  // float4 index
    if (i >= NN * (DD / 4)) return;
    int c4 = (i & 31) * 4;
    const float inv = 1.f / (float)NN;
    float4 s  = *(const float4*)&g_stats[c4];
    float4 s2 = *(const float4*)&g_stats[DD + c4];
    float4 gm = *(const float4*)&gamma[c4];
    float4 bt = *(const float4*)&beta[c4];
    float4 t = ((const float4*)g_T)[i];
    float4 h = ((const float4*)g_H)[i];
#define BN_ONE(X)                                                        \
    {                                                                    \
        float mu = s.X * inv;                                            \
        float var = s2.X * inv - mu * mu;                                \
        float rs = rsqrtf(var + 1e-5f);                                  \
        float v = (t.X - mu) * rs * gm.X + bt.X;                         \
        h.X += fmaxf(v, 0.f);                                            \
    }
    BN_ONE(x) BN_ONE(y) BN_ONE(z) BN_ONE(w)
#undef BN_ONE
    ((float4*)g_H)[i] = h;
}

// ---------------- pooling + readout ------------------------------------------
__global__ void k_pool(const int* __restrict__ n2g) {
    int w = (blockIdx.x * blockDim.x + threadIdx.x) >> 5;
    if (w >= NN) return;
    int lane = threadIdx.x & 31;
    int g = __ldg(&n2g[w]);
    float4 v = *(const float4*)(g_H + (size_t)w * DD + lane * 4);
    red_add_v4(g_pool + (size_t)g * DD + lane * 4, v);
    if (lane == 0) atomicAdd(&g_cnt[g], 1);
}

__global__ void k_readout(const float* __restrict__ W0, const float* __restrict__ b0,
                          const float* __restrict__ W1, const float* __restrict__ b1,
                          const float* __restrict__ W2, const float* __restrict__ b2,
                          float* __restrict__ out) {
    __shared__ float hg[128], y0[64], y1[32];
    int g = blockIdx.x;
    int t = threadIdx.x;
    float cnt = fmaxf((float)g_cnt[g], 1.f);
    hg[t] = g_pool[g * DD + t] / cnt;
    __syncthreads();
    if (t < 64) {
        float s = b0[t];
#pragma unroll 8
        for (int k = 0; k < 128; k++) s += hg[k] * W0[k * 64 + t];
        y0[t] = fmaxf(s, 0.f);
    }
    __syncthreads();
    if (t < 32) {
        float s = b1[t];
#pragma unroll 8
        for (int k = 0; k < 64; k++) s += y0[k] * W1[k * 32 + t];
        y1[t] = fmaxf(s, 0.f);
    }
    __syncthreads();
    float s = b2[t];
#pragma unroll
    for (int k = 0; k < 32; k++) s += y1[k] * W2[k * 128 + t];
    out[g * 128 + t] = s;
}

// ---------------- driver ------------------------------------------------------
extern "C" void kernel_launch(void* const* d_in, const int* in_sizes, int n_in,
                              void* d_out, int out_size) {
    const int*   h_idx    = (const int*)d_in[0];
    // d_in[1] = e_idx (unused), d_in[6] = bond_emb (unused)
    const int*   src      = (const int*)d_in[2];
    const int*   dst      = (const int*)d_in[3];
    const int*   n2g      = (const int*)d_in[4];
    const float* atom_emb = (const float*)d_in[5];
    const float* layer_W  = (const float*)d_in[7];
    const float* gamma    = (const float*)d_in[8];
    const float* beta     = (const float*)d_in[9];
    const float* W0       = (const float*)d_in[10];
    const float* b0       = (const float*)d_in[11];
    const float* W1       = (const float*)d_in[12];
    const float* b1       = (const float*)d_in[13];
    const float* W2       = (const float*)d_in[14];
    const float* b2       = (const float*)d_in[15];
    float* out = (float*)d_out;

    k_init <<<(NN + 255) / 256, 256>>>();
    k_embed<<<(NN * 32 + 255) / 256, 256>>>(h_idx, atom_emb);
    k_count<<<(EE + 255) / 256, 256>>>(dst);
    k_dsqrt<<<(NN + 255) / 256, 256>>>();
    k_edgew<<<(EE + 255) / 256, 256>>>(src, dst);

    for (int l = 0; l < LL; l++) {
        k_prep<<<(NN * 32 + 255) / 256, 256>>>();
        k_edge<<<(EE * 32 + 255) / 256, 256>>>(0, src, dst, -1.f);
        k_edge<<<(EE * 32 + 255) / 256, 256>>>(1, src, dst, -2.f);
        k_gemm<<<(NN + BM - 1) / BM, 256>>>(layer_W + (size_t)l * 3 * DD * DD);
        k_stats<<<(NN + 255) / 256, 256>>>();
        k_bnres<<<(NN * 32 + 255) / 256, 256>>>(gamma + l * DD, beta + l * DD);
    }

    k_pool<<<(NN * 32 + 255) / 256, 256>>>(n2g);
    k_readout<<<BB, 128>>>(W0, b0, W1, b1, W2, b2, out);
}

// round 3
// speedup vs baseline: 1.2394x; 1.2394x over previous
#include <cuda_runtime.h>
#include <cuda_bf16.h>

#define NN 50000
#define EE 800000
#define BB 256
#define DD 128
#define LL 4

// ---------------- scratch (static device globals; no runtime alloc) ----------
__device__ __align__(16) float g_H [(size_t)NN * DD];
__device__ __align__(16) float g_X1[(size_t)NN * DD];
__device__ __align__(16) float g_X2[(size_t)NN * DD];
__device__ __align__(16) float g_T [(size_t)NN * DD];
__device__ __align__(16) float g_dsq[NN];
__device__ __align__(16) float g_w  [EE];
__device__            int    g_deg [NN];
__device__ __align__(16) float g_stats[2 * DD];
__device__ __align__(16) float g_pool [BB * DD];
__device__            int    g_cnt  [BB];

__device__ __forceinline__ void red_add_v4(float* p, float4 v) {
    asm volatile("red.global.add.v4.f32 [%0], {%1,%2,%3,%4};"
                 :: "l"(p), "f"(v.x), "f"(v.y), "f"(v.z), "f"(v.w) : "memory");
}

__device__ __forceinline__ unsigned f2tf32(float f) {
    unsigned r;
    asm("cvt.rna.tf32.f32 %0, %1;" : "=r"(r) : "f"(f));
    return r;
}

// ---------------- setup kernels ----------------------------------------------
__global__ void k_init() {
    int i = blockIdx.x * blockDim.x + threadIdx.x;
    if (i < NN) g_deg[i] = 0;
    if (i < BB * DD) g_pool[i] = 0.f;
    if (i < BB) g_cnt[i] = 0;
}

// one warp per node; lane handles 4 channels (float4)
__global__ void k_embed(const int* __restrict__ h_idx,
                        const float* __restrict__ atom_emb) {
    int w = (blockIdx.x * blockDim.x + threadIdx.x) >> 5;
    if (w >= NN) return;
    int lane = threadIdx.x & 31;
    float4 acc = make_float4(0.f, 0.f, 0.f, 0.f);
#pragma unroll
    for (int f = 0; f < 9; f++) {
        int id = __ldg(&h_idx[w * 9 + f]);
        const float4* p = (const float4*)(atom_emb + ((size_t)f * 100 + id) * DD);
        float4 v = p[lane];
        acc.x += v.x; acc.y += v.y; acc.z += v.z; acc.w += v.w;
    }
    *(float4*)(g_H + (size_t)w * DD + lane * 4) = acc;
}

__global__ void k_count(const int* __restrict__ dst) {
    int e = blockIdx.x * blockDim.x + threadIdx.x;
    if (e < EE) atomicAdd(&g_deg[dst[e]], 1);
}

__global__ void k_dsqrt() {
    int i = blockIdx.x * blockDim.x + threadIdx.x;
    if (i < NN) {
        float d = (float)max(g_deg[i], 1);
        g_dsq[i] = rsqrtf(d);
    }
}

__global__ void k_edgew(const int* __restrict__ src, const int* __restrict__ dst) {
    int e = blockIdx.x * blockDim.x + threadIdx.x;
    if (e < EE) g_w[e] = g_dsq[src[e]] * g_dsq[dst[e]];
}

// ---------------- per-layer kernels ------------------------------------------
// X1 = 0 ; X2 = -H ; stats = 0
__global__ void k_prep() {
    int i = blockIdx.x * blockDim.x + threadIdx.x;  // float4 index
    if (i < NN * (DD / 4)) {
        ((float4*)g_X1)[i] = make_float4(0.f, 0.f, 0.f, 0.f);
        float4 h = ((const float4*)g_H)[i];
        ((float4*)g_X2)[i] = make_float4(-h.x, -h.y, -h.z, -h.w);
    }
    if (blockIdx.x == 0 && threadIdx.x < 2 * DD) g_stats[threadIdx.x] = 0.f;
}

// mode 0: X1 += coef * w_e * H[src]   (coef = -1)
// mode 1: X2 += coef * w_e * X1[src]  (coef = -2)
__global__ void k_edge(int mode, const int* __restrict__ src,
                       const int* __restrict__ dst, float coef) {
    int e = (blockIdx.x * blockDim.x + threadIdx.x) >> 5;
    if (e >= EE) return;
    int lane = threadIdx.x & 31;
    const float* x = (mode == 0) ? g_H : g_X1;
    float* out     = (mode == 0) ? g_X1 : g_X2;
    int s = __ldg(&src[e]);
    int d = __ldg(&dst[e]);
    float ww = __ldg(&g_w[e]) * coef;
    float4 v = *(const float4*)(x + (size_t)s * DD + lane * 4);
    red_add_v4(out + (size_t)d * DD + lane * 4,
               make_float4(v.x * ww, v.y * ww, v.z * ww, v.w * ww));
}

// ------------- tf32 tensor-core GEMM: T = [H|X1|X2] @ W  ---------------------
// block tile 128 rows x 128 cols, K=384 in 12 chunks of 32.
// 8 warps: warp w -> rows (w&3)*32..+31, cols (w>>2)*64..+63
// each warp: 2 (m16) x 8 (n8) mma tiles, k8 steps.
#define AST 36    // A smem row stride (floats), conflict-free frag loads
#define BST 136   // B smem row stride (floats)
__global__ void __launch_bounds__(256, 2) k_gemm_tc(const float* __restrict__ W) {
    __shared__ unsigned As[128 * AST];
    __shared__ unsigned Bs[32 * BST];
    int tid  = threadIdx.x;
    int lane = tid & 31;
    int wid  = tid >> 5;
    int wr = wid & 3;           // row group (32 rows)
    int wc = wid >> 2;          // col half (64 cols)
    int g  = lane >> 2;         // groupID 0..7
    int t  = lane & 3;          // thread-in-group
    int row0 = blockIdx.x * 128;

    float c[2][8][4];
#pragma unroll
    for (int i = 0; i < 2; i++)
#pragma unroll
        for (int j = 0; j < 8; j++)
#pragma unroll
            for (int q = 0; q < 4; q++) c[i][j][q] = 0.f;

    for (int kt = 0; kt < 12; kt++) {
        int k0 = kt * 32;
        const float* srcm = (k0 < DD) ? g_H : ((k0 < 2 * DD) ? g_X1 : g_X2);
        int kin0 = k0 & (DD - 1);
        // A tile: 128 rows x 32 k  (1024 float4, 4 per thread)
#pragma unroll
        for (int i = 0; i < 4; i++) {
            int id = tid + i * 256;
            int r = id >> 3, c4 = (id & 7) * 4;
            float4 v = make_float4(0.f, 0.f, 0.f, 0.f);
            if (row0 + r < NN)
                v = *(const float4*)(srcm + (size_t)(row0 + r) * DD + kin0 + c4);
            unsigned* p = &As[r * AST + c4];
            p[0] = f2tf32(v.x); p[1] = f2tf32(v.y);
            p[2] = f2tf32(v.z); p[3] = f2tf32(v.w);
        }
        // B tile: 32 k x 128 cols
#pragma unroll
        for (int i = 0; i < 4; i++) {
            int id = tid + i * 256;
            int kr = id >> 5, c4 = (id & 31) * 4;
            float4 v = *(const float4*)(W + (size_t)(k0 + kr) * DD + c4);
            unsigned* p = &Bs[kr * BST + c4];
            p[0] = f2tf32(v.x); p[1] = f2tf32(v.y);
            p[2] = f2tf32(v.z); p[3] = f2tf32(v.w);
        }
        __syncthreads();
#pragma unroll
        for (int kk = 0; kk < 4; kk++) {
            int kb = kk * 8;
            unsigned a[2][4];
#pragma unroll
            for (int mt = 0; mt < 2; mt++) {
                int rb = wr * 32 + mt * 16;
                a[mt][0] = As[(rb + g)     * AST + kb + t];
                a[mt][1] = As[(rb + g + 8) * AST + kb + t];
                a[mt][2] = As[(rb + g)     * AST + kb + t + 4];
                a[mt][3] = As[(rb + g + 8) * AST + kb + t + 4];
            }
            unsigned b[8][2];
#pragma unroll
            for (int nt = 0; nt < 8; nt++) {
                int cb = wc * 64 + nt * 8 + g;
                b[nt][0] = Bs[(kb + t)     * BST + cb];
                b[nt][1] = Bs[(kb + t + 4) * BST + cb];
            }
#pragma unroll
            for (int mt = 0; mt < 2; mt++)
#pragma unroll
                for (int nt = 0; nt < 8; nt++) {
                    asm volatile(
                        "mma.sync.aligned.m16n8k8.row.col.f32.tf32.tf32.f32 "
                        "{%0,%1,%2,%3}, {%4,%5,%6,%7}, {%8,%9}, {%0,%1,%2,%3};"
                        : "+f"(c[mt][nt][0]), "+f"(c[mt][nt][1]),
                          "+f"(c[mt][nt][2]), "+f"(c[mt][nt][3])
                        : "r"(a[mt][0]), "r"(a[mt][1]), "r"(a[mt][2]), "r"(a[mt][3]),
                          "r"(b[nt][0]), "r"(b[nt][1]));
                }
        }
        __syncthreads();
    }
    // epilogue
#pragma unroll
    for (int mt = 0; mt < 2; mt++) {
        int r0 = row0 + wr * 32 + mt * 16 + g;
        int r1 = r0 + 8;
#pragma unroll
        for (int nt = 0; nt < 8; nt++) {
            int col = wc * 64 + nt * 8 + t * 2;
            if (r0 < NN)
                *(float2*)(g_T + (size_t)r0 * DD + col) =
                    make_float2(c[mt][nt][0], c[mt][nt][1]);
            if (r1 < NN)
                *(float2*)(g_T + (size_t)r1 * DD + col) =
                    make_float2(c[mt][nt][2], c[mt][nt][3]);
        }
    }
}

// per-channel sum & sumsq over T
__global__ void k_stats() {
    __shared__ float sh1[256], sh2[256];
    int col = threadIdx.x & 127;
    int half = threadIdx.x >> 7;
    int r0 = blockIdx.x * 256;
    int rend = min(r0 + 256, NN);
    float s = 0.f, s2 = 0.f;
    for (int r = r0 + half; r < rend; r += 2) {
        float v = g_T[(size_t)r * DD + col];
        s += v; s2 += v * v;
    }
    sh1[threadIdx.x] = s;
    sh2[threadIdx.x] = s2;
    __syncthreads();
    if (half == 0) {
        atomicAdd(&g_stats[col],      s  + sh1[threadIdx.x + 128]);
        atomicAdd(&g_stats[DD + col], s2 + sh2[threadIdx.x + 128]);
    }
}

// H += relu( (T - mu) * rstd * gamma + beta )
__global__ void k_bnres(const float* __restrict__ gamma,
                        const float* __restrict__ beta) {
    int i = blockIdx.x * blockDim.x + threadIdx.x;  // float4 index
    if (i >= NN * (DD / 4)) return;
    int c4 = (i & 31) * 4;
    const float inv = 1.f / (float)NN;
    float4 s  = *(const float4*)&g_stats[c4];
    float4 s2 = *(const float4*)&g_stats[DD + c4];
    float4 gm = *(const float4*)&gamma[c4];
    float4 bt = *(const float4*)&beta[c4];
    float4 t = ((const float4*)g_T)[i];
    float4 h = ((const float4*)g_H)[i];
#define BN_ONE(X)                                                        \
    {                                                                    \
        float mu = s.X * inv;                                            \
        float var = s2.X * inv - mu * mu;                                \
        float rs = rsqrtf(var + 1e-5f);                                  \
        float v = (t.X - mu) * rs * gm.X + bt.X;                         \
        h.X += fmaxf(v, 0.f);                                            \
    }
    BN_ONE(x) BN_ONE(y) BN_ONE(z) BN_ONE(w)
#undef BN_ONE
    ((float4*)g_H)[i] = h;
}

// ---------------- pooling + readout ------------------------------------------
__global__ void k_pool(const int* __restrict__ n2g) {
    int w = (blockIdx.x * blockDim.x + threadIdx.x) >> 5;
    if (w >= NN) return;
    int lane = threadIdx.x & 31;
    int g = __ldg(&n2g[w]);
    float4 v = *(const float4*)(g_H + (size_t)w * DD + lane * 4);
    red_add_v4(g_pool + (size_t)g * DD + lane * 4, v);
    if (lane == 0) atomicAdd(&g_cnt[g], 1);
}

__global__ void k_readout(const float* __restrict__ W0, const float* __restrict__ b0,
                          const float* __restrict__ W1, const float* __restrict__ b1,
                          const float* __restrict__ W2, const float* __restrict__ b2,
                          float* __restrict__ out) {
    __shared__ float hg[128], y0[64], y1[32];
    int g = blockIdx.x;
    int t = threadIdx.x;
    float cnt = fmaxf((float)g_cnt[g], 1.f);
    hg[t] = g_pool[g * DD + t] / cnt;
    __syncthreads();
    if (t < 64) {
        float s = b0[t];
#pragma unroll 8
        for (int k = 0; k < 128; k++) s += hg[k] * W0[k * 64 + t];
        y0[t] = fmaxf(s, 0.f);
    }
    __syncthreads();
    if (t < 32) {
        float s = b1[t];
#pragma unroll 8
        for (int k = 0; k < 64; k++) s += y0[k] * W1[k * 32 + t];
        y1[t] = fmaxf(s, 0.f);
    }
    __syncthreads();
    float s = b2[t];
#pragma unroll
    for (int k = 0; k < 32; k++) s += y1[k] * W2[k * 128 + t];
    out[g * 128 + t] = s;
}

// ---------------- driver ------------------------------------------------------
extern "C" void kernel_launch(void* const* d_in, const int* in_sizes, int n_in,
                              void* d_out, int out_size) {
    const int*   h_idx    = (const int*)d_in[0];
    // d_in[1] = e_idx (unused), d_in[6] = bond_emb (unused)
    const int*   src      = (const int*)d_in[2];
    const int*   dst      = (const int*)d_in[3];
    const int*   n2g      = (const int*)d_in[4];
    const float* atom_emb = (const float*)d_in[5];
    const float* layer_W  = (const float*)d_in[7];
    const float* gamma    = (const float*)d_in[8];
    const float* beta     = (const float*)d_in[9];
    const float* W0       = (const float*)d_in[10];
    const float* b0       = (const float*)d_in[11];
    const float* W1       = (const float*)d_in[12];
    const float* b1       = (const float*)d_in[13];
    const float* W2       = (const float*)d_in[14];
    const float* b2       = (const float*)d_in[15];
    float* out = (float*)d_out;

    k_init <<<(NN + 255) / 256, 256>>>();
    k_embed<<<(NN * 32 + 255) / 256, 256>>>(h_idx, atom_emb);
    k_count<<<(EE + 255) / 256, 256>>>(dst);
    k_dsqrt<<<(NN + 255) / 256, 256>>>();
    k_edgew<<<(EE + 255) / 256, 256>>>(src, dst);

    for (int l = 0; l < LL; l++) {
        k_prep<<<(NN * 32 + 255) / 256, 256>>>();
        k_edge<<<(EE * 32 + 255) / 256, 256>>>(0, src, dst, -1.f);
        k_edge<<<(EE * 32 + 255) / 256, 256>>>(1, src, dst, -2.f);
        k_gemm_tc<<<(NN + 127) / 128, 256>>>(layer_W + (size_t)l * 3 * DD * DD);
        k_stats<<<(NN + 255) / 256, 256>>>();
        k_bnres<<<(NN * 32 + 255) / 256, 256>>>(gamma + l * DD, beta + l * DD);
    }

    k_pool<<<(NN * 32 + 255) / 256, 256>>>(n2g);
    k_readout<<<BB, 128>>>(W0, b0, W1, b1, W2, b2, out);
}

// round 8
// speedup vs baseline: 2.3684x; 1.9110x over previous
#include <cuda_runtime.h>
#include <cuda_bf16.h>

#define NN 50000
#define EE 800000
#define BB 256
#define DD 128
#define LL 4

// ---------------- scratch (static device globals; no runtime alloc) ----------
__device__ __align__(16) float g_H [(size_t)NN * DD];
__device__ __align__(16) float g_S1[(size_t)NN * DD];
__device__ __align__(16) float g_S2[(size_t)NN * DD];
__device__ __align__(16) float g_T [(size_t)NN * DD];
__device__ __align__(16) float g_dsq[NN];
__device__            int    g_deg [NN];
__device__            int    g_rowp[NN];
__device__            int    g_cur [NN];
__device__            int    g_btot[256];
__device__            int    g_bbase[256];
__device__            int    g_csrc[EE];
__device__ __align__(16) float g_cw [EE];
__device__ __align__(16) float g_Wmod[(size_t)LL * 3 * DD * DD];
__device__ __align__(16) float g_stats[2 * DD];
__device__ __align__(16) float g_pool [BB * DD];
__device__            int    g_cnt  [BB];

#define SCAN_B 196   // ceil(NN/256)

__device__ __forceinline__ void red_add_v4(float* p, float4 v) {
    asm volatile("red.global.add.v4.f32 [%0], {%1,%2,%3,%4};"
                 :: "l"(p), "f"(v.x), "f"(v.y), "f"(v.z), "f"(v.w) : "memory");
}

__device__ __forceinline__ unsigned f2tf32(float f) {
    unsigned r;
    asm("cvt.rna.tf32.f32 %0, %1;" : "=r"(r) : "f"(f));
    return r;
}

// ---------------- setup kernels ----------------------------------------------
__global__ void k_init() {
    int i = blockIdx.x * blockDim.x + threadIdx.x;
    if (i < NN) g_deg[i] = 0;
    if (i < BB * DD) g_pool[i] = 0.f;
    if (i < BB) g_cnt[i] = 0;
}

// one warp per node; lane handles 4 channels (float4)
__global__ void k_embed(const int* __restrict__ h_idx,
                        const float* __restrict__ atom_emb) {
    int w = (blockIdx.x * blockDim.x + threadIdx.x) >> 5;
    if (w >= NN) return;
    int lane = threadIdx.x & 31;
    float4 acc = make_float4(0.f, 0.f, 0.f, 0.f);
#pragma unroll
    for (int f = 0; f < 9; f++) {
        int id = __ldg(&h_idx[w * 9 + f]);
        const float4* p = (const float4*)(atom_emb + ((size_t)f * 100 + id) * DD);
        float4 v = p[lane];
        acc.x += v.x; acc.y += v.y; acc.z += v.z; acc.w += v.w;
    }
    *(float4*)(g_H + (size_t)w * DD + lane * 4) = acc;
}

__global__ void k_count(const int* __restrict__ dst) {
    int e = blockIdx.x * blockDim.x + threadIdx.x;
    if (e < EE) atomicAdd(&g_deg[dst[e]], 1);
}

// per-256-node block: exclusive scan of deg (no base), block total
__global__ void k_scan1() {
    __shared__ int sh[256];
    int t = threadIdx.x;
    int i = blockIdx.x * 256 + t;
    int v = (i < NN) ? g_deg[i] : 0;
    sh[t] = v;
    __syncthreads();
#pragma unroll
    for (int off = 1; off < 256; off <<= 1) {
        int x = (t >= off) ? sh[t - off] : 0;
        __syncthreads();
        sh[t] += x;
        __syncthreads();
    }
    if (i < NN) g_rowp[i] = sh[t] - v;           // exclusive, no base
    if (t == 255) g_btot[blockIdx.x] = sh[255];
}

// scan block totals (exclusive)
__global__ void k_scan2() {
    __shared__ int sh[256];
    int t = threadIdx.x;
    int v = (t < SCAN_B) ? g_btot[t] : 0;
    sh[t] = v;
    __syncthreads();
#pragma unroll
    for (int off = 1; off < 256; off <<= 1) {
        int x = (t >= off) ? sh[t - off] : 0;
        __syncthreads();
        sh[t] += x;
        __syncthreads();
    }
    if (t < SCAN_B) g_bbase[t] = sh[t] - v;
}

// add base; init cursor; compute dsq
__global__ void k_scan3() {
    int i = blockIdx.x * blockDim.x + threadIdx.x;
    if (i >= NN) return;
    int p = g_rowp[i] + g_bbase[i >> 8];
    g_rowp[i] = p;
    g_cur[i] = p;
    g_dsq[i] = rsqrtf((float)max(g_deg[i], 1));
}

__global__ void k_place(const int* __restrict__ src, const int* __restrict__ dst) {
    int e = blockIdx.x * blockDim.x + threadIdx.x;
    if (e >= EE) return;
    int d = dst[e], s = src[e];
    int pos = atomicAdd(&g_cur[d], 1);
    g_csrc[pos] = s;
    g_cw[pos] = g_dsq[s] * g_dsq[d];
}

// Wmod = [W0 - W2 ; -W1 ; 2*W2] per layer
__global__ void k_wmod(const float* __restrict__ W) {
    int i = blockIdx.x * blockDim.x + threadIdx.x;
    if (i >= LL * 3 * DD * DD) return;
    int l = i / (3 * DD * DD);
    int r = i - l * (3 * DD * DD);
    int k = r >> 7;               // 0..383
    const float* Wl = W + (size_t)l * 3 * DD * DD;
    float v;
    if (k < DD)            v = Wl[r] - Wl[r + 2 * DD * DD];
    else if (k < 2 * DD)   v = -Wl[r];
    else                   v = 2.f * Wl[r];
    g_Wmod[i] = v;
}

// ---------------- propagation: out[d,:] = sum_e w_e * x[src_e,:] -------------
// mode 0: g_H -> g_S1 ; mode 1: g_S1 -> g_S2   (device-side symbol access!)
__global__ void __launch_bounds__(256) k_prop(int mode) {
    int w = (blockIdx.x * blockDim.x + threadIdx.x) >> 5;
    if (w >= NN) return;
    const float* x   = (mode == 0) ? g_H  : g_S1;
    float*       out = (mode == 0) ? g_S1 : g_S2;
    int lane = threadIdx.x & 31;
    int beg = g_rowp[w];
    int n = g_deg[w];
    int end = beg + n;
    float4 acc = make_float4(0.f, 0.f, 0.f, 0.f);
    int e = beg;
    for (; e + 2 <= end; e += 2) {
        int s0 = __ldg(&g_csrc[e]);
        int s1 = __ldg(&g_csrc[e + 1]);
        float w0 = __ldg(&g_cw[e]);
        float w1 = __ldg(&g_cw[e + 1]);
        float4 v0 = *(const float4*)(x + (size_t)s0 * DD + lane * 4);
        float4 v1 = *(const float4*)(x + (size_t)s1 * DD + lane * 4);
        acc.x += w0 * v0.x + w1 * v1.x;
        acc.y += w0 * v0.y + w1 * v1.y;
        acc.z += w0 * v0.z + w1 * v1.z;
        acc.w += w0 * v0.w + w1 * v1.w;
    }
    if (e < end) {
        int s0 = __ldg(&g_csrc[e]);
        float w0 = __ldg(&g_cw[e]);
        float4 v0 = *(const float4*)(x + (size_t)s0 * DD + lane * 4);
        acc.x += w0 * v0.x; acc.y += w0 * v0.y;
        acc.z += w0 * v0.z; acc.w += w0 * v0.w;
    }
    *(float4*)(out + (size_t)w * DD + lane * 4) = acc;
}

__global__ void k_zstats() {
    if (threadIdx.x < 2 * DD) g_stats[threadIdx.x] = 0.f;
}

// ------------- tf32 tensor-core GEMM: T = [H|S1|S2] @ Wmod[l] ----------------
#define AST 36
#define BST 136
__global__ void __launch_bounds__(256, 2) k_gemm_tc(int layer) {
    const float* W = g_Wmod + (size_t)layer * 3 * DD * DD;  // device-side address
    __shared__ unsigned As[128 * AST];
    __shared__ unsigned Bs[32 * BST];
    int tid  = threadIdx.x;
    int lane = tid & 31;
    int wid  = tid >> 5;
    int wr = wid & 3;
    int wc = wid >> 2;
    int g  = lane >> 2;
    int t  = lane & 3;
    int row0 = blockIdx.x * 128;

    float c[2][8][4];
#pragma unroll
    for (int i = 0; i < 2; i++)
#pragma unroll
        for (int j = 0; j < 8; j++)
#pragma unroll
            for (int q = 0; q < 4; q++) c[i][j][q] = 0.f;

    for (int kt = 0; kt < 12; kt++) {
        int k0 = kt * 32;
        const float* srcm = (k0 < DD) ? g_H : ((k0 < 2 * DD) ? g_S1 : g_S2);
        int kin0 = k0 & (DD - 1);
#pragma unroll
        for (int i = 0; i < 4; i++) {
            int id = tid + i * 256;
            int r = id >> 3, c4 = (id & 7) * 4;
            float4 v = make_float4(0.f, 0.f, 0.f, 0.f);
            if (row0 + r < NN)
                v = *(const float4*)(srcm + (size_t)(row0 + r) * DD + kin0 + c4);
            unsigned* p = &As[r * AST + c4];
            p[0] = f2tf32(v.x); p[1] = f2tf32(v.y);
            p[2] = f2tf32(v.z); p[3] = f2tf32(v.w);
        }
#pragma unroll
        for (int i = 0; i < 4; i++) {
            int id = tid + i * 256;
            int kr = id >> 5, c4 = (id & 31) * 4;
            float4 v = *(const float4*)(W + (size_t)(k0 + kr) * DD + c4);
            unsigned* p = &Bs[kr * BST + c4];
            p[0] = f2tf32(v.x); p[1] = f2tf32(v.y);
            p[2] = f2tf32(v.z); p[3] = f2tf32(v.w);
        }
        __syncthreads();
#pragma unroll
        for (int kk = 0; kk < 4; kk++) {
            int kb = kk * 8;
            unsigned a[2][4];
#pragma unroll
            for (int mt = 0; mt < 2; mt++) {
                int rb = wr * 32 + mt * 16;
                a[mt][0] = As[(rb + g)     * AST + kb + t];
                a[mt][1] = As[(rb + g + 8) * AST + kb + t];
                a[mt][2] = As[(rb + g)     * AST + kb + t + 4];
                a[mt][3] = As[(rb + g + 8) * AST + kb + t + 4];
            }
            unsigned b[8][2];
#pragma unroll
            for (int nt = 0; nt < 8; nt++) {
                int cb = wc * 64 + nt * 8 + g;
                b[nt][0] = Bs[(kb + t)     * BST + cb];
                b[nt][1] = Bs[(kb + t + 4) * BST + cb];
            }
#pragma unroll
            for (int mt = 0; mt < 2; mt++)
#pragma unroll
                for (int nt = 0; nt < 8; nt++) {
                    asm volatile(
                        "mma.sync.aligned.m16n8k8.row.col.f32.tf32.tf32.f32 "
                        "{%0,%1,%2,%3}, {%4,%5,%6,%7}, {%8,%9}, {%0,%1,%2,%3};"
                        : "+f"(c[mt][nt][0]), "+f"(c[mt][nt][1]),
                          "+f"(c[mt][nt][2]), "+f"(c[mt][nt][3])
                        : "r"(a[mt][0]), "r"(a[mt][1]), "r"(a[mt][2]), "r"(a[mt][3]),
                          "r"(b[nt][0]), "r"(b[nt][1]));
                }
        }
        __syncthreads();
    }
#pragma unroll
    for (int mt = 0; mt < 2; mt++) {
        int r0 = row0 + wr * 32 + mt * 16 + g;
        int r1 = r0 + 8;
#pragma unroll
        for (int nt = 0; nt < 8; nt++) {
            int col = wc * 64 + nt * 8 + t * 2;
            if (r0 < NN)
                *(float2*)(g_T + (size_t)r0 * DD + col) =
                    make_float2(c[mt][nt][0], c[mt][nt][1]);
            if (r1 < NN)
                *(float2*)(g_T + (size_t)r1 * DD + col) =
                    make_float2(c[mt][nt][2], c[mt][nt][3]);
        }
    }
}

// per-channel sum & sumsq over T
__global__ void k_stats() {
    __shared__ float sh1[256], sh2[256];
    int col = threadIdx.x & 127;
    int half = threadIdx.x >> 7;
    int r0 = blockIdx.x * 256;
    int rend = min(r0 + 256, NN);
    float s = 0.f, s2 = 0.f;
    for (int r = r0 + half; r < rend; r += 2) {
        float v = g_T[(size_t)r * DD + col];
        s += v; s2 += v * v;
    }
    sh1[threadIdx.x] = s;
    sh2[threadIdx.x] = s2;
    __syncthreads();
    if (half == 0) {
        atomicAdd(&g_stats[col],      s  + sh1[threadIdx.x + 128]);
        atomicAdd(&g_stats[DD + col], s2 + sh2[threadIdx.x + 128]);
    }
}

// H += relu( (T - mu) * rstd * gamma + beta )
__global__ void k_bnres(const float* __restrict__ gamma,
                        const float* __restrict__ beta) {
    int i = blockIdx.x * blockDim.x + threadIdx.x;
    if (i >= NN * (DD / 4)) return;
    int c4 = (i & 31) * 4;
    const float inv = 1.f / (float)NN;
    float4 s  = *(const float4*)&g_stats[c4];
    float4 s2 = *(const float4*)&g_stats[DD + c4];
    float4 gm = *(const float4*)&gamma[c4];
    float4 bt = *(const float4*)&beta[c4];
    float4 t = ((const float4*)g_T)[i];
    float4 h = ((const float4*)g_H)[i];
#define BN_ONE(X)                                                        \
    {                                                                    \
        float mu = s.X * inv;                                            \
        float var = s2.X * inv - mu * mu;                                \
        float rs = rsqrtf(var + 1e-5f);                                  \
        float v = (t.X - mu) * rs * gm.X + bt.X;                         \
        h.X += fmaxf(v, 0.f);                                            \
    }
    BN_ONE(x) BN_ONE(y) BN_ONE(z) BN_ONE(w)
#undef BN_ONE
    ((float4*)g_H)[i] = h;
}

// ---------------- pooling + readout ------------------------------------------
__global__ void k_pool(const int* __restrict__ n2g) {
    int w = (blockIdx.x * blockDim.x + threadIdx.x) >> 5;
    if (w >= NN) return;
    int lane = threadIdx.x & 31;
    int g = __ldg(&n2g[w]);
    float4 v = *(const float4*)(g_H + (size_t)w * DD + lane * 4);
    red_add_v4(g_pool + (size_t)g * DD + lane * 4, v);
    if (lane == 0) atomicAdd(&g_cnt[g], 1);
}

__global__ void k_readout(const float* __restrict__ W0, const float* __restrict__ b0,
                          const float* __restrict__ W1, const float* __restrict__ b1,
                          const float* __restrict__ W2, const float* __restrict__ b2,
                          float* __restrict__ out) {
    __shared__ float hg[128], y0[64], y1[32];
    int g = blockIdx.x;
    int t = threadIdx.x;
    float cnt = fmaxf((float)g_cnt[g], 1.f);
    hg[t] = g_pool[g * DD + t] / cnt;
    __syncthreads();
    if (t < 64) {
        float s = b0[t];
#pragma unroll 8
        for (int k = 0; k < 128; k++) s += hg[k] * W0[k * 64 + t];
        y0[t] = fmaxf(s, 0.f);
    }
    __syncthreads();
    if (t < 32) {
        float s = b1[t];
#pragma unroll 8
        for (int k = 0; k < 64; k++) s += y0[k] * W1[k * 32 + t];
        y1[t] = fmaxf(s, 0.f);
    }
    __syncthreads();
    float s = b2[t];
#pragma unroll
    for (int k = 0; k < 32; k++) s += y1[k] * W2[k * 128 + t];
    out[g * 128 + t] = s;
}

// ---------------- driver ------------------------------------------------------
extern "C" void kernel_launch(void* const* d_in, const int* in_sizes, int n_in,
                              void* d_out, int out_size) {
    const int*   h_idx    = (const int*)d_in[0];
    // d_in[1] = e_idx (unused), d_in[6] = bond_emb (unused)
    const int*   src      = (const int*)d_in[2];
    const int*   dst      = (const int*)d_in[3];
    const int*   n2g      = (const int*)d_in[4];
    const float* atom_emb = (const float*)d_in[5];
    const float* layer_W  = (const float*)d_in[7];
    const float* gamma    = (const float*)d_in[8];
    const float* beta     = (const float*)d_in[9];
    const float* W0       = (const float*)d_in[10];
    const float* b0       = (const float*)d_in[11];
    const float* W1       = (const float*)d_in[12];
    const float* b1       = (const float*)d_in[13];
    const float* W2       = (const float*)d_in[14];
    const float* b2       = (const float*)d_in[15];
    float* out = (float*)d_out;

    k_init <<<(NN + 255) / 256, 256>>>();
    k_embed<<<(NN * 32 + 255) / 256, 256>>>(h_idx, atom_emb);
    k_count<<<(EE + 255) / 256, 256>>>(dst);
    k_scan1<<<SCAN_B, 256>>>();
    k_scan2<<<1, 256>>>();
    k_scan3<<<(NN + 255) / 256, 256>>>();
    k_place<<<(EE + 255) / 256, 256>>>(src, dst);
    k_wmod <<<(LL * 3 * DD * DD + 255) / 256, 256>>>(layer_W);

    for (int l = 0; l < LL; l++) {
        k_prop<<<(NN * 32 + 255) / 256, 256>>>(0);
        k_prop<<<(NN * 32 + 255) / 256, 256>>>(1);
        k_zstats<<<1, 256>>>();
        k_gemm_tc<<<(NN + 127) / 128, 256>>>(l);
        k_stats<<<(NN + 255) / 256, 256>>>();
        k_bnres<<<(NN * 32 + 255) / 256, 256>>>(gamma + l * DD, beta + l * DD);
    }

    k_pool<<<(NN * 32 + 255) / 256, 256>>>(n2g);
    k_readout<<<BB, 128>>>(W0, b0, W1, b1, W2, b2, out);
}

// round 9
// speedup vs baseline: 2.9639x; 1.2514x over previous
#include <cuda_runtime.h>
#include <cuda_bf16.h>

#define NN 50000
#define EE 800000
#define BB 256
#define DD 128
#define LL 4

// ---------------- scratch (static device globals; no runtime alloc) ----------
__device__ __align__(16) float    g_H [(size_t)NN * DD];      // fp32 master
__device__ __align__(16) unsigned g_Hb [(size_t)NN * DD / 2]; // bf16x2 packed
__device__ __align__(16) unsigned g_S1b[(size_t)NN * DD / 2];
__device__ __align__(16) unsigned g_S2b[(size_t)NN * DD / 2];
__device__ __align__(16) float    g_T [(size_t)NN * DD];
__device__ __align__(16) float    g_dsq[NN];
__device__            int    g_deg [NN];
__device__            int    g_rowp[NN];
__device__            int    g_cur [NN];
__device__            int    g_btot[256];
__device__            int    g_bbase[256];
__device__            int    g_csrc[EE];
__device__ __align__(16) float g_cw [EE];
__device__ __align__(16) unsigned g_Wmodb[(size_t)LL * 192 * DD]; // bf16x2, k2-major
__device__ __align__(16) float g_stats[2 * DD];
__device__ __align__(16) float g_pool [BB * DD];
__device__            int    g_cnt  [BB];

#define SCAN_B 196   // ceil(NN/256)

__device__ __forceinline__ void red_add_v4(float* p, float4 v) {
    asm volatile("red.global.add.v4.f32 [%0], {%1,%2,%3,%4};"
                 :: "l"(p), "f"(v.x), "f"(v.y), "f"(v.z), "f"(v.w) : "memory");
}

__device__ __forceinline__ unsigned packbf(float a, float b) {
    __nv_bfloat162 p = __floats2bfloat162_rn(a, b);
    return *(unsigned*)&p;
}
__device__ __forceinline__ float2 unpackbf(unsigned u) {
    return __bfloat1622float2(*(__nv_bfloat162*)&u);
}

// ---------------- setup kernels ----------------------------------------------
__global__ void k_init() {
    int i = blockIdx.x * blockDim.x + threadIdx.x;
    if (i < NN) g_deg[i] = 0;
    if (i < BB * DD) g_pool[i] = 0.f;
    if (i < BB) g_cnt[i] = 0;
}

// one warp per node; lane handles 4 channels
__global__ void k_embed(const int* __restrict__ h_idx,
                        const float* __restrict__ atom_emb) {
    int w = (blockIdx.x * blockDim.x + threadIdx.x) >> 5;
    if (w >= NN) return;
    int lane = threadIdx.x & 31;
    float4 acc = make_float4(0.f, 0.f, 0.f, 0.f);
#pragma unroll
    for (int f = 0; f < 9; f++) {
        int id = __ldg(&h_idx[w * 9 + f]);
        const float4* p = (const float4*)(atom_emb + ((size_t)f * 100 + id) * DD);
        float4 v = p[lane];
        acc.x += v.x; acc.y += v.y; acc.z += v.z; acc.w += v.w;
    }
    int i = w * 32 + lane;
    ((float4*)g_H)[i] = acc;
    ((uint2*)g_Hb)[i] = make_uint2(packbf(acc.x, acc.y), packbf(acc.z, acc.w));
}

__global__ void k_count(const int* __restrict__ dst) {
    int e = blockIdx.x * blockDim.x + threadIdx.x;
    if (e < EE) atomicAdd(&g_deg[dst[e]], 1);
}

__global__ void k_scan1() {
    __shared__ int sh[256];
    int t = threadIdx.x;
    int i = blockIdx.x * 256 + t;
    int v = (i < NN) ? g_deg[i] : 0;
    sh[t] = v;
    __syncthreads();
#pragma unroll
    for (int off = 1; off < 256; off <<= 1) {
        int x = (t >= off) ? sh[t - off] : 0;
        __syncthreads();
        sh[t] += x;
        __syncthreads();
    }
    if (i < NN) g_rowp[i] = sh[t] - v;
    if (t == 255) g_btot[blockIdx.x] = sh[255];
}

__global__ void k_scan2() {
    __shared__ int sh[256];
    int t = threadIdx.x;
    int v = (t < SCAN_B) ? g_btot[t] : 0;
    sh[t] = v;
    __syncthreads();
#pragma unroll
    for (int off = 1; off < 256; off <<= 1) {
        int x = (t >= off) ? sh[t - off] : 0;
        __syncthreads();
        sh[t] += x;
        __syncthreads();
    }
    if (t < SCAN_B) g_bbase[t] = sh[t] - v;
}

__global__ void k_scan3() {
    int i = blockIdx.x * blockDim.x + threadIdx.x;
    if (i >= NN) return;
    int p = g_rowp[i] + g_bbase[i >> 8];
    g_rowp[i] = p;
    g_cur[i] = p;
    g_dsq[i] = rsqrtf((float)max(g_deg[i], 1));
}

__global__ void k_place(const int* __restrict__ src, const int* __restrict__ dst) {
    int e = blockIdx.x * blockDim.x + threadIdx.x;
    if (e >= EE) return;
    int d = dst[e], s = src[e];
    int pos = atomicAdd(&g_cur[d], 1);
    g_csrc[pos] = s;
    g_cw[pos] = g_dsq[s] * g_dsq[d];
}

// Wmod = [W0 - W2 ; -W1 ; 2*W2], bf16x2-packed over k pairs: [l][k2][col]
__global__ void k_wmod(const float* __restrict__ W) {
    int i = blockIdx.x * blockDim.x + threadIdx.x;
    if (i >= LL * 192 * DD) return;
    int l = i / (192 * DD);
    int rem = i - l * (192 * DD);
    int k2 = rem >> 7;
    int col = rem & 127;
    const float* Wl = W + (size_t)l * 3 * DD * DD;
    float v[2];
#pragma unroll
    for (int q = 0; q < 2; q++) {
        int k = 2 * k2 + q;
        float w = Wl[k * DD + col];
        if (k < DD)            v[q] = w - Wl[(k + 2 * DD) * DD + col];
        else if (k < 2 * DD)   v[q] = -w;
        else                   v[q] = 2.f * w;
    }
    g_Wmodb[i] = packbf(v[0], v[1]);
}

// ---------------- propagation (bf16 gather, fp32 accumulate) -----------------
// mode 0: g_Hb -> g_S1b ; mode 1: g_S1b -> g_S2b
__global__ void __launch_bounds__(256) k_prop(int mode) {
    int w = (blockIdx.x * blockDim.x + threadIdx.x) >> 5;
    if (w >= NN) return;
    const uint2* x   = (mode == 0) ? (const uint2*)g_Hb  : (const uint2*)g_S1b;
    uint2*       out = (mode == 0) ? (uint2*)g_S1b : (uint2*)g_S2b;
    int lane = threadIdx.x & 31;
    int beg = g_rowp[w];
    int end = beg + g_deg[w];
    float4 acc = make_float4(0.f, 0.f, 0.f, 0.f);
    int e = beg;
    for (; e + 2 <= end; e += 2) {
        int s0 = __ldg(&g_csrc[e]);
        int s1 = __ldg(&g_csrc[e + 1]);
        float w0 = __ldg(&g_cw[e]);
        float w1 = __ldg(&g_cw[e + 1]);
        uint2 u0 = x[(size_t)s0 * 32 + lane];
        uint2 u1 = x[(size_t)s1 * 32 + lane];
        float2 a0 = unpackbf(u0.x), b0 = unpackbf(u0.y);
        float2 a1 = unpackbf(u1.x), b1 = unpackbf(u1.y);
        acc.x += w0 * a0.x + w1 * a1.x;
        acc.y += w0 * a0.y + w1 * a1.y;
        acc.z += w0 * b0.x + w1 * b1.x;
        acc.w += w0 * b0.y + w1 * b1.y;
    }
    if (e < end) {
        int s0 = __ldg(&g_csrc[e]);
        float w0 = __ldg(&g_cw[e]);
        uint2 u0 = x[(size_t)s0 * 32 + lane];
        float2 a0 = unpackbf(u0.x), b0 = unpackbf(u0.y);
        acc.x += w0 * a0.x; acc.y += w0 * a0.y;
        acc.z += w0 * b0.x; acc.w += w0 * b0.y;
    }
    out[(size_t)w * 32 + lane] = make_uint2(packbf(acc.x, acc.y), packbf(acc.z, acc.w));
}

// ------------- bf16 tensor-core GEMM: T = [H|S1|S2] @ Wmod[l] ----------------
// A tile 128x32(k) as u32 pairs: 128 x 16 u32, stride 20 (conflict-free frags)
// B tile 32(k) x 128  as u32 pairs: 16 x 128 u32, stride 136
#define AST2 20
#define BST2 136
__global__ void __launch_bounds__(256, 2) k_gemm_tc(int layer) {
    const unsigned* Wb = g_Wmodb + (size_t)layer * 192 * DD;
    __shared__ unsigned As[128 * AST2];
    __shared__ unsigned Bs[16 * BST2];
    int tid  = threadIdx.x;
    int lane = tid & 31;
    int wid  = tid >> 5;
    int wr = wid & 3;
    int wc = wid >> 2;
    int g  = lane >> 2;
    int t  = lane & 3;
    int row0 = blockIdx.x * 128;

    if (blockIdx.x == 0 && tid < 2 * DD) g_stats[tid] = 0.f;  // stream-ordered before k_stats

    float c[2][8][4];
#pragma unroll
    for (int i = 0; i < 2; i++)
#pragma unroll
        for (int j = 0; j < 8; j++)
#pragma unroll
            for (int q = 0; q < 4; q++) c[i][j][q] = 0.f;

    for (int kt = 0; kt < 12; kt++) {
        int k0 = kt * 32;
        const unsigned* srcm = (k0 < DD) ? g_Hb : ((k0 < 2 * DD) ? g_S1b : g_S2b);
        int kin32 = (k0 & (DD - 1)) >> 1;   // u32 offset within row (row = 64 u32)
        // A tile: 128 rows x 16 u32 ; 512 uint4 loads, 2 per thread
#pragma unroll
        for (int i = 0; i < 2; i++) {
            int id = tid + i * 256;
            int r = id >> 2, cc = (id & 3) * 4;
            uint4 v = make_uint4(0u, 0u, 0u, 0u);
            if (row0 + r < NN)
                v = *(const uint4*)(srcm + (size_t)(row0 + r) * 64 + kin32 + cc);
            *(uint4*)&As[r * AST2 + cc] = v;
        }
        // B tile: 16 k2 x 128 cols ; 512 uint4, 2 per thread
#pragma unroll
        for (int i = 0; i < 2; i++) {
            int id = tid + i * 256;
            int k2 = id >> 5, cc = (id & 31) * 4;
            *(uint4*)&Bs[k2 * BST2 + cc] =
                *(const uint4*)(Wb + (size_t)(kt * 16 + k2) * DD + cc);
        }
        __syncthreads();
#pragma unroll
        for (int kk = 0; kk < 2; kk++) {
            int kb2 = kk * 8;     // u32 (k-pair) base: covers k16
            unsigned a[2][4];
#pragma unroll
            for (int mt = 0; mt < 2; mt++) {
                int rb = wr * 32 + mt * 16;
                a[mt][0] = As[(rb + g)     * AST2 + kb2 + t];
                a[mt][1] = As[(rb + g + 8) * AST2 + kb2 + t];
                a[mt][2] = As[(rb + g)     * AST2 + kb2 + t + 4];
                a[mt][3] = As[(rb + g + 8) * AST2 + kb2 + t + 4];
            }
            unsigned b[8][2];
#pragma unroll
            for (int nt = 0; nt < 8; nt++) {
                int cb = wc * 64 + nt * 8 + g;
                b[nt][0] = Bs[(kb2 + t)     * BST2 + cb];
                b[nt][1] = Bs[(kb2 + t + 4) * BST2 + cb];
            }
#pragma unroll
            for (int mt = 0; mt < 2; mt++)
#pragma unroll
                for (int nt = 0; nt < 8; nt++) {
                    asm volatile(
                        "mma.sync.aligned.m16n8k16.row.col.f32.bf16.bf16.f32 "
                        "{%0,%1,%2,%3}, {%4,%5,%6,%7}, {%8,%9}, {%0,%1,%2,%3};"
                        : "+f"(c[mt][nt][0]), "+f"(c[mt][nt][1]),
                          "+f"(c[mt][nt][2]), "+f"(c[mt][nt][3])
                        : "r"(a[mt][0]), "r"(a[mt][1]), "r"(a[mt][2]), "r"(a[mt][3]),
                          "r"(b[nt][0]), "r"(b[nt][1]));
                }
        }
        __syncthreads();
    }
#pragma unroll
    for (int mt = 0; mt < 2; mt++) {
        int r0 = row0 + wr * 32 + mt * 16 + g;
        int r1 = r0 + 8;
#pragma unroll
        for (int nt = 0; nt < 8; nt++) {
            int col = wc * 64 + nt * 8 + t * 2;
            if (r0 < NN)
                *(float2*)(g_T + (size_t)r0 * DD + col) =
                    make_float2(c[mt][nt][0], c[mt][nt][1]);
            if (r1 < NN)
                *(float2*)(g_T + (size_t)r1 * DD + col) =
                    make_float2(c[mt][nt][2], c[mt][nt][3]);
        }
    }
}

// per-channel sum & sumsq over T
__global__ void k_stats() {
    __shared__ float sh1[256], sh2[256];
    int col = threadIdx.x & 127;
    int half = threadIdx.x >> 7;
    int r0 = blockIdx.x * 256;
    int rend = min(r0 + 256, NN);
    float s = 0.f, s2 = 0.f;
    for (int r = r0 + half; r < rend; r += 2) {
        float v = g_T[(size_t)r * DD + col];
        s += v; s2 += v * v;
    }
    sh1[threadIdx.x] = s;
    sh2[threadIdx.x] = s2;
    __syncthreads();
    if (half == 0) {
        atomicAdd(&g_stats[col],      s  + sh1[threadIdx.x + 128]);
        atomicAdd(&g_stats[DD + col], s2 + sh2[threadIdx.x + 128]);
    }
}

// H += relu( (T - mu) * rstd * gamma + beta ) ; also refresh bf16 copy
__global__ void k_bnres(const float* __restrict__ gamma,
                        const float* __restrict__ beta) {
    int i = blockIdx.x * blockDim.x + threadIdx.x;
    if (i >= NN * (DD / 4)) return;
    int c4 = (i & 31) * 4;
    const float inv = 1.f / (float)NN;
    float4 s  = *(const float4*)&g_stats[c4];
    float4 s2 = *(const float4*)&g_stats[DD + c4];
    float4 gm = *(const float4*)&gamma[c4];
    float4 bt = *(const float4*)&beta[c4];
    float4 t = ((const float4*)g_T)[i];
    float4 h = ((const float4*)g_H)[i];
#define BN_ONE(X)                                                        \
    {                                                                    \
        float mu = s.X * inv;                                            \
        float var = s2.X * inv - mu * mu;                                \
        float rs = rsqrtf(var + 1e-5f);                                  \
        float v = (t.X - mu) * rs * gm.X + bt.X;                         \
        h.X += fmaxf(v, 0.f);                                            \
    }
    BN_ONE(x) BN_ONE(y) BN_ONE(z) BN_ONE(w)
#undef BN_ONE
    ((float4*)g_H)[i] = h;
    ((uint2*)g_Hb)[i] = make_uint2(packbf(h.x, h.y), packbf(h.z, h.w));
}

// ---------------- pooling + readout ------------------------------------------
__global__ void k_pool(const int* __restrict__ n2g) {
    int w = (blockIdx.x * blockDim.x + threadIdx.x) >> 5;
    if (w >= NN) return;
    int lane = threadIdx.x & 31;
    int g = __ldg(&n2g[w]);
    float4 v = *(const float4*)(g_H + (size_t)w * DD + lane * 4);
    red_add_v4(g_pool + (size_t)g * DD + lane * 4, v);
    if (lane == 0) atomicAdd(&g_cnt[g], 1);
}

__global__ void k_readout(const float* __restrict__ W0, const float* __restrict__ b0,
                          const float* __restrict__ W1, const float* __restrict__ b1,
                          const float* __restrict__ W2, const float* __restrict__ b2,
                          float* __restrict__ out) {
    __shared__ float hg[128], y0[64], y1[32];
    int g = blockIdx.x;
    int t = threadIdx.x;
    float cnt = fmaxf((float)g_cnt[g], 1.f);
    hg[t] = g_pool[g * DD + t] / cnt;
    __syncthreads();
    if (t < 64) {
        float s = b0[t];
#pragma unroll 8
        for (int k = 0; k < 128; k++) s += hg[k] * W0[k * 64 + t];
        y0[t] = fmaxf(s, 0.f);
    }
    __syncthreads();
    if (t < 32) {
        float s = b1[t];
#pragma unroll 8
        for (int k = 0; k < 64; k++) s += y0[k] * W1[k * 32 + t];
        y1[t] = fmaxf(s, 0.f);
    }
    __syncthreads();
    float s = b2[t];
#pragma unroll
    for (int k = 0; k < 32; k++) s += y1[k] * W2[k * 128 + t];
    out[g * 128 + t] = s;
}

// ---------------- driver ------------------------------------------------------
extern "C" void kernel_launch(void* const* d_in, const int* in_sizes, int n_in,
                              void* d_out, int out_size) {
    const int*   h_idx    = (const int*)d_in[0];
    // d_in[1] = e_idx (unused), d_in[6] = bond_emb (unused)
    const int*   src      = (const int*)d_in[2];
    const int*   dst      = (const int*)d_in[3];
    const int*   n2g      = (const int*)d_in[4];
    const float* atom_emb = (const float*)d_in[5];
    const float* layer_W  = (const float*)d_in[7];
    const float* gamma    = (const float*)d_in[8];
    const float* beta     = (const float*)d_in[9];
    const float* W0       = (const float*)d_in[10];
    const float* b0       = (const float*)d_in[11];
    const float* W1       = (const float*)d_in[12];
    const float* b1       = (const float*)d_in[13];
    const float* W2       = (const float*)d_in[14];
    const float* b2       = (const float*)d_in[15];
    float* out = (float*)d_out;

    k_init <<<(NN + 255) / 256, 256>>>();
    k_embed<<<(NN * 32 + 255) / 256, 256>>>(h_idx, atom_emb);
    k_count<<<(EE + 255) / 256, 256>>>(dst);
    k_scan1<<<SCAN_B, 256>>>();
    k_scan2<<<1, 256>>>();
    k_scan3<<<(NN + 255) / 256, 256>>>();
    k_place<<<(EE + 255) / 256, 256>>>(src, dst);
    k_wmod <<<(LL * 192 * DD + 255) / 256, 256>>>(layer_W);

    for (int l = 0; l < LL; l++) {
        k_prop<<<(NN * 32 + 255) / 256, 256>>>(0);
        k_prop<<<(NN * 32 + 255) / 256, 256>>>(1);
        k_gemm_tc<<<(NN + 127) / 128, 256>>>(l);
        k_stats<<<(NN + 255) / 256, 256>>>();
        k_bnres<<<(NN * 32 + 255) / 256, 256>>>(gamma + l * DD, beta + l * DD);
    }

    k_pool<<<(NN * 32 + 255) / 256, 256>>>(n2g);
    k_readout<<<BB, 128>>>(W0, b0, W1, b1, W2, b2, out);
}